// round 17
// baseline (speedup 1.0000x reference)
#include <cuda_runtime.h>
#include <cstdint>

// Conv2d VALID: x[32,64,112,112] f32, w[128,64,3,3] f32 -> out[32,128,110,110] f32
// Implicit GEMM via mma.sync.m16n8k8 tf32.
// Round 17: R16 design with the B store/read layout mismatch FIXED.
//   A: perm col = q*8+g*2+e, A_STRIDE=36 -> LDS.128 frags (phase-conflict-free)
//   B: s-invariant window as (k,k+4) float2 pairs, layout Bs2[cell*17 + kp]
//      used by BOTH the STS staging (hoisted sidx) and the LDS.64 frags.
//   Gather decode stays kp-major (coalesced LDG); goff+sidx packed in one u32.

namespace {

constexpr int CIN = 64, COUT = 128, H = 112, W = 112, OH = 110, OW = 110;
constexpr int HW = H * W;
constexpr int A_STRIDE = 36;
constexpr int A_BYTES = 128 * A_STRIDE * 4;   // 18432
constexpr int B_CELLS = 2 * 68;               // osub x col = 136 cells
constexpr int B_F2 = B_CELLS * 17;            // 2312 float2 per window (16 kp + 1 pad)
constexpr int B_BYTES = B_F2 * 8;             // 18496
constexpr int B_PAIRS = B_CELLS * 16;         // 2176 real pairs = 8.5 * 256
constexpr int SM_TOTAL = 2 * A_BYTES + 2 * B_BYTES;   // 73856

__device__ float g_A_pre[18 * 4096];  // [kc = half*9 + r*3 + s][co 128][perm-col 32]

__device__ __forceinline__ float to_tf32(float v) {
    float o;
    asm("cvt.rna.tf32.f32 %0, %1;" : "=f"(o) : "f"(v));
    return o;
}
__device__ __forceinline__ uint32_t smem_u32(const void* p) {
    uint32_t a;
    asm("{ .reg .u64 t; cvta.to.shared.u64 t, %1; cvt.u32.u64 %0, t; }" : "=r"(a) : "l"(p));
    return a;
}
__device__ __forceinline__ void cp_async16(uint32_t dst, const void* src) {
    asm volatile("cp.async.ca.shared.global [%0], [%1], 16;" :: "r"(dst), "l"(src));
}
__device__ __forceinline__ void cp_commit() {
    asm volatile("cp.async.commit_group;" ::: "memory");
}
__device__ __forceinline__ void cp_wait0() {
    asm volatile("cp.async.wait_group 0;" ::: "memory");
}
__device__ __forceinline__ void sts_f32x2(uint32_t addr, float v0, float v1) {
    asm volatile("st.shared.v2.f32 [%0], {%1, %2};" :: "r"(addr), "f"(v0), "f"(v1) : "memory");
}

// perm-col = q*8 + g*2 + e  <->  k = g*8 + q + 4*e ;  kc = half*9 + r*3 + s
__global__ void prep_weights(const float* __restrict__ w) {
    int idx = blockIdx.x * 256 + threadIdx.x;   // 0 .. 73727
    int kc  = idx >> 12;
    int rem = idx & 4095;
    int co  = rem >> 5;
    int col = rem & 31;
    int q = col >> 3, g = (col & 7) >> 1, e = col & 1;
    int k    = g * 8 + q + 4 * e;
    int half = kc / 9;
    int rs   = kc - half * 9;
    int ci   = half * 32 + k;
    g_A_pre[idx] = to_tf32(w[((size_t)co * CIN + ci) * 9 + rs]);
}

__global__ __launch_bounds__(256, 2)
void conv_mma(const float* __restrict__ x, float* __restrict__ out)
{
    extern __shared__ char sm[];   // A0 | A1 | B0 | B1

    const int tid  = threadIdx.x;
    const int lane = tid & 31;
    const int wid  = tid >> 5;
    const int wm   = wid >> 2;
    const int wn   = wid & 3;
    const int lr   = lane >> 2;
    const int lq   = lane & 3;

    const int ow0 = blockIdx.x * 64;
    const int oh0 = blockIdx.y * 2;
    const int bb  = blockIdx.z;

    const float* xb = x + (size_t)bb * CIN * HW;
    const uint32_t smbase = smem_u32(sm);
    const uint32_t bwin0  = smbase + (uint32_t)(2 * A_BYTES);

    // ---- hoisted gather slots: packed (sidx<<19 | goff), chunk-invariant ----
    // flat = tid + 256*i (kp-major: kp = flat/136, cell = flat%136 -> coalesced LDG)
    // store index sidx = cell*17 + kp  (cell-major, matches fragment reads)
    uint32_t pk[9];
#pragma unroll
    for (int i = 0; i < 9; ++i) {
        int flat = tid + 256 * i;
        if (flat >= B_PAIRS) flat = B_PAIRS - 1;       // slot 8, tid>=128: never stored
        int kp   = flat / 136;
        int cell = flat - kp * 136;
        int osub = cell / 68;
        int col  = cell - osub * 68;
        int k    = (kp & 3) * 8 + (kp >> 2);
        uint32_t goff = (uint32_t)(k * HW + osub * W + min(ow0 + col, W - 1));
        uint32_t sidx = (uint32_t)(cell * 17 + kp);
        pk[i] = (sidx << 19) | goff;
    }
    const bool slot8 = (tid < 128);

    uint32_t a_dst[4];
#pragma unroll
    for (int i = 0; i < 4; ++i) {
        int idx = tid + 256 * i;
        a_dst[i] = smbase + (uint32_t)((idx >> 3) * A_STRIDE + (idx & 7) * 4) * 4;
    }

    float acc[4][4][4];
#pragma unroll
    for (int i = 0; i < 4; i++)
#pragma unroll
        for (int j = 0; j < 4; j++)
#pragma unroll
            for (int k = 0; k < 4; k++) acc[i][j][k] = 0.0f;

    // ---- prologue: stage-0 window (half=0, r=0) + A chunk 0 ----
    {
        const float* srcb0 = xb + oh0 * W;
#pragma unroll
        for (int i = 0; i < 9; ++i) {
            if (i < 8 || slot8) {
                uint32_t go = pk[i] & 0x7FFFFu;
                uint32_t sa = bwin0 + (pk[i] >> 19) * 8u;
                sts_f32x2(sa, to_tf32(srcb0[go]), to_tf32(srcb0[go + 4 * HW]));
            }
        }
        const float4* src = (const float4*)g_A_pre;
#pragma unroll
        for (int i = 0; i < 4; ++i) cp_async16(a_dst[i], src + tid + 256 * i);
        cp_commit();
    }

    for (int j = 0; j < 6; ++j) {               // stage = (half, r)
        const int jn    = j + 1;
        const int halfn = jn / 3;
        const int rn    = jn - halfn * 3;
        const float* srcb = xb + (size_t)halfn * 32 * HW + (oh0 + rn) * W;

#pragma unroll
        for (int s = 0; s < 3; ++s) {
            const int kc = j * 3 + s;

            cp_wait0();
            __syncthreads();   // A[kc] ready; all warps done with prior tap

            // ---- A prefetch chunk kc+1 ----
            if (kc < 17) {
                const float4* src = (const float4*)(g_A_pre + (kc + 1) * 4096);
                const uint32_t ab = ((kc + 1) & 1) ? (uint32_t)A_BYTES : 0u;
#pragma unroll
                for (int i = 0; i < 4; ++i) cp_async16(a_dst[i] + ab, src + tid + 256 * i);
                cp_commit();
            }

            // ---- B pair-gather for stage j+1 (slots s*3 ..) ----
            float pv0[3], pv1[3];
            if (j < 5) {
#pragma unroll
                for (int u = 0; u < 3; ++u) {
                    const int slot = s * 3 + u;
                    pv0[u] = 0.0f; pv1[u] = 0.0f;
                    if (slot < 8 || slot8) {
                        uint32_t go = pk[slot] & 0x7FFFFu;
                        pv0[u] = srcb[go];
                        pv1[u] = srcb[go + 4 * HW];
                    }
                }
            }

            // ---- compute tap ----
            const float*  As  = (const float*)(sm + (kc & 1) * A_BYTES);
            const float2* Bw2 = (const float2*)(sm + 2 * A_BYTES + (j & 1) * B_BYTES)
                                + ((wn >> 1) * 68 + (wn & 1) * 32 + s + lr) * 17 + lq * 4;

#pragma unroll
            for (int gp = 0; gp < 2; ++gp) {
                uint32_t a[4][2][4];
#pragma unroll
                for (int mf = 0; mf < 4; ++mf) {
                    int row = wm * 64 + mf * 16 + lr;
                    float4 u0 = *(const float4*)(As + row * A_STRIDE + lq * 8 + gp * 4);
                    float4 u1 = *(const float4*)(As + (row + 8) * A_STRIDE + lq * 8 + gp * 4);
                    a[mf][0][0] = __float_as_uint(u0.x);
                    a[mf][0][1] = __float_as_uint(u1.x);
                    a[mf][0][2] = __float_as_uint(u0.y);
                    a[mf][0][3] = __float_as_uint(u1.y);
                    a[mf][1][0] = __float_as_uint(u0.z);
                    a[mf][1][1] = __float_as_uint(u1.z);
                    a[mf][1][2] = __float_as_uint(u0.w);
                    a[mf][1][3] = __float_as_uint(u1.w);
                }
                uint32_t b[4][2][2];
#pragma unroll
                for (int nf = 0; nf < 4; ++nf) {
#pragma unroll
                    for (int gs = 0; gs < 2; ++gs) {
                        float2 v = Bw2[nf * 8 * 17 + gp * 2 + gs];
                        b[nf][gs][0] = __float_as_uint(v.x);
                        b[nf][gs][1] = __float_as_uint(v.y);
                    }
                }
#pragma unroll
                for (int mf = 0; mf < 4; ++mf)
#pragma unroll
                    for (int nf = 0; nf < 4; ++nf)
#pragma unroll
                        for (int gs = 0; gs < 2; ++gs) {
                            asm volatile(
                                "mma.sync.aligned.m16n8k8.row.col.f32.tf32.tf32.f32 "
                                "{%0,%1,%2,%3}, {%4,%5,%6,%7}, {%8,%9}, {%0,%1,%2,%3};"
                                : "+f"(acc[mf][nf][0]), "+f"(acc[mf][nf][1]),
                                  "+f"(acc[mf][nf][2]), "+f"(acc[mf][nf][3])
                                : "r"(a[mf][gs][0]), "r"(a[mf][gs][1]),
                                  "r"(a[mf][gs][2]), "r"(a[mf][gs][3]),
                                  "r"(b[nf][gs][0]), "r"(b[nf][gs][1]));
                        }
            }

            // ---- STS gathered pairs into next window buffer ----
            if (j < 5) {
                const uint32_t bd = bwin0 + (((j + 1) & 1) ? (uint32_t)B_BYTES : 0u);
#pragma unroll
                for (int u = 0; u < 3; ++u) {
                    const int slot = s * 3 + u;
                    if (slot < 8 || slot8)
                        sts_f32x2(bd + (pk[slot] >> 19) * 8u,
                                  to_tf32(pv0[u]), to_tf32(pv1[u]));
                }
            }
        }
    }

    // ---- epilogue: direct STG.64 (even ow, pairs in-bounds) ----
#pragma unroll
    for (int mf = 0; mf < 4; ++mf) {
#pragma unroll
        for (int nf = 0; nf < 4; ++nf) {
            int nglob = wn * 32 + nf * 8 + lq * 2;    // even
            int osub  = nglob >> 6;
            int ow    = ow0 + (nglob & 63);
            int oh    = oh0 + osub;
            if (ow < OW) {
                int co0 = wm * 64 + mf * 16 + lr;
                float* p0 = out + (((size_t)bb * COUT + co0) * OH + oh) * OW + ow;
                *(float2*)p0 = make_float2(acc[mf][nf][0], acc[mf][nf][1]);
                float* p1 = p0 + (size_t)8 * OH * OW;
                *(float2*)p1 = make_float2(acc[mf][nf][2], acc[mf][nf][3]);
            }
        }
    }
}

} // namespace

extern "C" void kernel_launch(void* const* d_in, const int* in_sizes, int n_in,
                              void* d_out, int out_size)
{
    const float* x = (const float*)d_in[0];
    const float* w = (const float*)d_in[1];
    float* out = (float*)d_out;

    cudaFuncSetAttribute(conv_mma, cudaFuncAttributeMaxDynamicSharedMemorySize, SM_TOTAL);

    prep_weights<<<18 * 4096 / 256, 256>>>(w);

    dim3 grid(2, 55, 32);   // ow tiles (2x64), oh pairs, batch
    conv_mma<<<grid, 256, SM_TOTAL>>>(x, out);
}